// round 1
// baseline (speedup 1.0000x reference)
#include <cuda_runtime.h>
#include <cstddef>

#define BATCH 64
#define DIM 512
#define MAT (DIM * DIM)          // 262144
#define NUM_ITER 5

typedef unsigned long long ull;

// Scratch (allocation-free rule: __device__ globals).
__device__ float g_Y[2][(size_t)BATCH * MAT];
__device__ float g_Z[2][(size_t)BATCH * MAT];
__device__ float g_T[(size_t)BATCH * MAT];
__device__ float g_norm[BATCH];

// ---------------- packed f32x2 helpers (sm_100+) ----------------
__device__ __forceinline__ ull pkdup(float v) {
    ull r;
    asm("mov.b64 %0, {%1, %1};" : "=l"(r) : "f"(v));
    return r;
}
__device__ __forceinline__ void fma2(ull& d, ull a, ull b) {
    asm("fma.rn.f32x2 %0, %1, %2, %0;" : "+l"(d) : "l"(a), "l"(b));
}
__device__ __forceinline__ float2 upk(ull v) {
    float2 f;
    asm("mov.b64 {%0, %1}, %2;" : "=f"(f.x), "=f"(f.y) : "l"(v));
    return f;
}

// ---------------- Frobenius norm per batch ----------------
__global__ void norm_kernel(const float* __restrict__ x) {
    const int b = blockIdx.x;
    const float4* xb = (const float4*)(x + (size_t)b * MAT);
    float s = 0.f;
    for (int i = threadIdx.x; i < MAT / 4; i += blockDim.x) {
        float4 v = xb[i];
        s += v.x * v.x + v.y * v.y + v.z * v.z + v.w * v.w;
    }
    __shared__ float red[8];
    #pragma unroll
    for (int o = 16; o; o >>= 1) s += __shfl_xor_sync(0xFFFFFFFFu, s, o);
    if ((threadIdx.x & 31) == 0) red[threadIdx.x >> 5] = s;
    __syncthreads();
    if (threadIdx.x < 32) {
        s = (threadIdx.x < (int)(blockDim.x >> 5)) ? red[threadIdx.x] : 0.f;
        #pragma unroll
        for (int o = 16; o; o >>= 1) s += __shfl_xor_sync(0xFFFFFFFFu, s, o);
        if (threadIdx.x == 0) g_norm[b] = sqrtf(s);
    }
}

// ---------------- Y0 = x / normA ; Z0 = I ----------------
__global__ void init_kernel(const float* __restrict__ x) {
    const int i = blockIdx.x * blockDim.x + threadIdx.x;
    if (i >= BATCH * MAT / 4) return;
    const int b = i / (MAT / 4);
    const float inv = 1.0f / g_norm[b];
    float4 v = ((const float4*)x)[i];
    v.x *= inv; v.y *= inv; v.z *= inv; v.w *= inv;
    ((float4*)g_Y[0])[i] = v;

    const int r = i % (MAT / 4);
    const int row = r / (DIM / 4);
    const int c4 = r % (DIM / 4);
    float4 z = make_float4(0.f, 0.f, 0.f, 0.f);
    if (c4 == (row >> 2)) ((float*)&z)[row & 3] = 1.0f;
    ((float4*)g_Z[0])[i] = z;
}

// ---------------- out = Y * sqrt(normA) ----------------
__global__ void final_kernel(const float* __restrict__ Y, float* __restrict__ out) {
    const int i = blockIdx.x * blockDim.x + threadIdx.x;
    if (i >= BATCH * MAT / 4) return;
    const int b = i / (MAT / 4);
    const float s = sqrtf(g_norm[b]);
    float4 v = ((const float4*)Y)[i];
    v.x *= s; v.y *= s; v.z *= s; v.w *= s;
    ((float4*)out)[i] = v;
}

// ---------------- batched SGEMM: C = A*B  (MODE 1: C = 1.5 I - 0.5 A*B) ----------------
// 128x128 tile, BK=16, 256 threads, 8x8 per thread via f32x2 packed FMA.
template <int MODE>
__global__ void __launch_bounds__(256) gemm_kernel(const float* __restrict__ Ag,
                                                   const float* __restrict__ Bg,
                                                   float* __restrict__ Cg) {
    const int b = blockIdx.z;
    const float* A  = Ag + (size_t)b * MAT;
    const float* Bp = Bg + (size_t)b * MAT;
    float*       C  = Cg + (size_t)b * MAT;
    const int bm = blockIdx.y * 128;
    const int bn = blockIdx.x * 128;
    const int tid = threadIdx.x;
    const int tx = tid & 15;
    const int ty = tid >> 4;

    __shared__ float As[16][128];   // k-major (transposed) -> m-contiguous fragment reads
    __shared__ float Bs[16][128];

    const int rA = tid >> 2;            // 0..63
    const int kA = (tid & 3) << 2;      // 0,4,8,12
    const int kB = tid >> 5;            // 0..7
    const int nB = (tid & 31) << 2;     // 0..124

    const float* Aptr = A + (size_t)(bm + rA) * DIM + kA;
    const float* Bptr = Bp + (size_t)kB * DIM + bn + nB;

    ull acc[4][8];
    #pragma unroll
    for (int p = 0; p < 4; ++p)
        #pragma unroll
        for (int j = 0; j < 8; ++j) acc[p][j] = 0ull;

    // register prefetch of stage 0
    float4 a0 = *(const float4*)(Aptr);
    float4 a1 = *(const float4*)(Aptr + 64 * DIM);
    float4 b0 = *(const float4*)(Bptr);
    float4 b1 = *(const float4*)(Bptr + 8 * DIM);

    for (int s = 0; s < DIM / 16; ++s) {
        __syncthreads();
        As[kA + 0][rA] = a0.x; As[kA + 1][rA] = a0.y;
        As[kA + 2][rA] = a0.z; As[kA + 3][rA] = a0.w;
        As[kA + 0][rA + 64] = a1.x; As[kA + 1][rA + 64] = a1.y;
        As[kA + 2][rA + 64] = a1.z; As[kA + 3][rA + 64] = a1.w;
        *(float4*)&Bs[kB][nB]     = b0;
        *(float4*)&Bs[kB + 8][nB] = b1;
        __syncthreads();

        if (s + 1 < DIM / 16) {   // overlap next-stage global loads with compute
            Aptr += 16;
            Bptr += 16 * DIM;
            a0 = *(const float4*)(Aptr);
            a1 = *(const float4*)(Aptr + 64 * DIM);
            b0 = *(const float4*)(Bptr);
            b1 = *(const float4*)(Bptr + 8 * DIM);
        }

        #pragma unroll
        for (int kk = 0; kk < 16; ++kk) {
            float4 av0 = *(const float4*)&As[kk][ty * 8];
            float4 av1 = *(const float4*)&As[kk][ty * 8 + 4];
            float4 bv0 = *(const float4*)&Bs[kk][tx * 8];
            float4 bv1 = *(const float4*)&Bs[kk][tx * 8 + 4];
            ull ap[4];
            ap[0] = ((const ull*)&av0)[0];  // rows (0,1) of this thread's 8
            ap[1] = ((const ull*)&av0)[1];  // rows (2,3)
            ap[2] = ((const ull*)&av1)[0];  // rows (4,5)
            ap[3] = ((const ull*)&av1)[1];  // rows (6,7)
            float bf[8] = {bv0.x, bv0.y, bv0.z, bv0.w, bv1.x, bv1.y, bv1.z, bv1.w};
            #pragma unroll
            for (int j = 0; j < 8; ++j) {
                ull bb = pkdup(bf[j]);
                #pragma unroll
                for (int p = 0; p < 4; ++p) fma2(acc[p][j], ap[p], bb);
            }
        }
    }

    // epilogue: unpack row-pairs, apply mode, vector stores
    #pragma unroll
    for (int p = 0; p < 4; ++p) {
        float clo[8], chi[8];
        #pragma unroll
        for (int j = 0; j < 8; ++j) {
            float2 v = upk(acc[p][j]);
            clo[j] = v.x; chi[j] = v.y;
        }
        const int r0 = bm + ty * 8 + 2 * p;
        const int r1 = r0 + 1;
        const int c0 = bn + tx * 8;
        if (MODE == 1) {
            #pragma unroll
            for (int j = 0; j < 8; ++j) {
                clo[j] = -0.5f * clo[j] + ((c0 + j == r0) ? 1.5f : 0.0f);
                chi[j] = -0.5f * chi[j] + ((c0 + j == r1) ? 1.5f : 0.0f);
            }
        }
        float4* dst0 = (float4*)(C + (size_t)r0 * DIM + c0);
        float4* dst1 = (float4*)(C + (size_t)r1 * DIM + c0);
        dst0[0] = make_float4(clo[0], clo[1], clo[2], clo[3]);
        dst0[1] = make_float4(clo[4], clo[5], clo[6], clo[7]);
        dst1[0] = make_float4(chi[0], chi[1], chi[2], chi[3]);
        dst1[1] = make_float4(chi[4], chi[5], chi[6], chi[7]);
    }
}

extern "C" void kernel_launch(void* const* d_in, const int* in_sizes, int n_in,
                              void* d_out, int out_size) {
    const float* x = (const float*)d_in[0];
    float* out = (float*)d_out;

    float *Yb, *Zb, *Tb;
    cudaGetSymbolAddress((void**)&Yb, g_Y);
    cudaGetSymbolAddress((void**)&Zb, g_Z);
    cudaGetSymbolAddress((void**)&Tb, g_T);
    float* Y[2] = {Yb, Yb + (size_t)BATCH * MAT};
    float* Z[2] = {Zb, Zb + (size_t)BATCH * MAT};

    norm_kernel<<<BATCH, 256>>>(x);

    const int total4 = BATCH * MAT / 4;
    init_kernel<<<(total4 + 255) / 256, 256>>>(x);

    dim3 ggrid(DIM / 128, DIM / 128, BATCH);
    int cur = 0;
    for (int it = 0; it < NUM_ITER; ++it) {
        // T = 1.5 I - 0.5 * Z @ Y
        gemm_kernel<1><<<ggrid, 256>>>(Z[cur], Y[cur], Tb);
        // Y' = Y @ T
        gemm_kernel<0><<<ggrid, 256>>>(Y[cur], Tb, Y[1 - cur]);
        // Z' = T @ Z
        gemm_kernel<0><<<ggrid, 256>>>(Tb, Z[cur], Z[1 - cur]);
        cur ^= 1;
    }

    final_kernel<<<(total4 + 255) / 256, 256>>>(Y[cur], out);
}

// round 3
// speedup vs baseline: 1.8844x; 1.8844x over previous
#include <cuda_runtime.h>
#include <cstdint>
#include <cstddef>

#define BATCH 64
#define DIM 512
#define MAT (DIM * DIM)
#define NUM_ITER 5
#define BK 16

typedef unsigned long long ull;

// ---------------- device scratch (allocation-free rule) ----------------
__device__ float g_Y[2][(size_t)BATCH * MAT];
__device__ float g_Z[2][(size_t)BATCH * MAT];
__device__ float g_T[(size_t)BATCH * MAT];
__device__ float g_norm[BATCH];

// upper-triangular tile pairs for a 4x4 tile grid (128-wide tiles)
__constant__ int c_ti[10] = {0, 0, 0, 0, 1, 1, 1, 2, 2, 3};
__constant__ int c_tj[10] = {0, 1, 2, 3, 1, 2, 3, 2, 3, 3};

// ---------------- packed f32x2 helpers ----------------
__device__ __forceinline__ ull pkdup(float v) {
    ull r;
    asm("mov.b64 %0, {%1, %1};" : "=l"(r) : "f"(v));
    return r;
}
__device__ __forceinline__ void fma2(ull& d, ull a, ull b) {
    asm("fma.rn.f32x2 %0, %1, %2, %0;" : "+l"(d) : "l"(a), "l"(b));
}
__device__ __forceinline__ float2 upk(ull v) {
    float2 f;
    asm("mov.b64 {%0, %1}, %2;" : "=f"(f.x), "=f"(f.y) : "l"(v));
    return f;
}
__device__ __forceinline__ uint32_t smem_u32(const void* p) {
    uint32_t a;
    asm("{ .reg .u64 t; cvta.to.shared.u64 t, %1; cvt.u32.u64 %0, t; }" : "=r"(a) : "l"(p));
    return a;
}
__device__ __forceinline__ void cp16(uint32_t dst, const void* src) {
    asm volatile("cp.async.cg.shared.global [%0], [%1], 16;" :: "r"(dst), "l"(src));
}

// ---------------- Frobenius norm per batch ----------------
__global__ void norm_kernel(const float* __restrict__ x) {
    const int b = blockIdx.x;
    const float4* xb = (const float4*)(x + (size_t)b * MAT);
    float s = 0.f;
    for (int i = threadIdx.x; i < MAT / 4; i += blockDim.x) {
        float4 v = xb[i];
        s += v.x * v.x + v.y * v.y + v.z * v.z + v.w * v.w;
    }
    __shared__ float red[8];
    #pragma unroll
    for (int o = 16; o; o >>= 1) s += __shfl_xor_sync(0xFFFFFFFFu, s, o);
    if ((threadIdx.x & 31) == 0) red[threadIdx.x >> 5] = s;
    __syncthreads();
    if (threadIdx.x < 32) {
        s = (threadIdx.x < (int)(blockDim.x >> 5)) ? red[threadIdx.x] : 0.f;
        #pragma unroll
        for (int o = 16; o; o >>= 1) s += __shfl_xor_sync(0xFFFFFFFFu, s, o);
        if (threadIdx.x == 0) g_norm[b] = sqrtf(s);
    }
}

// ---------------- Y0 = x / normA ----------------
__global__ void init_kernel(const float* __restrict__ x, float* __restrict__ Y0) {
    const int i = blockIdx.x * blockDim.x + threadIdx.x;
    if (i >= BATCH * MAT / 4) return;
    const int b = i / (MAT / 4);
    const float inv = 1.0f / g_norm[b];
    float4 v = ((const float4*)x)[i];
    v.x *= inv; v.y *= inv; v.z *= inv; v.w *= inv;
    ((float4*)Y0)[i] = v;
}

// ---------------- Z1 = T0 = 1.5 I - 0.5 * Y0 ----------------
__global__ void zt_kernel(const float* __restrict__ Y0, float* __restrict__ Z1) {
    const int i = blockIdx.x * blockDim.x + threadIdx.x;
    if (i >= BATCH * MAT / 4) return;
    float4 v = ((const float4*)Y0)[i];
    const int r = i % (MAT / 4);
    const int row = r / (DIM / 4);
    const int c4 = r % (DIM / 4);
    float4 o;
    o.x = -0.5f * v.x; o.y = -0.5f * v.y; o.z = -0.5f * v.z; o.w = -0.5f * v.w;
    if (c4 == (row >> 2)) ((float*)&o)[row & 3] += 1.5f;
    ((float4*)Z1)[i] = o;
}

// ---------------- out = Y * sqrt(normA) ----------------
__global__ void final_kernel(const float* __restrict__ Y, float* __restrict__ out) {
    const int i = blockIdx.x * blockDim.x + threadIdx.x;
    if (i >= BATCH * MAT / 4) return;
    const int b = i / (MAT / 4);
    const float s = sqrtf(g_norm[b]);
    float4 v = ((const float4*)Y)[i];
    v.x *= s; v.y *= s; v.z *= s; v.w *= s;
    ((float4*)out)[i] = v;
}

// ---------------- symmetric-output batched SGEMM ----------------
// C = A @ B (MODE 0) or C = 1.5 I - 0.5 * (A @ B) (MODE 1).
// Output is symmetric (all NS iterates are polynomials of symmetric A):
// only tiles ti<=tj computed; off-diagonal tiles mirror-stored transposed.
// 128x128 tile, BK=16, 256 threads, 8 rows x 4 n-pairs per thread via f32x2.
// 3-stage cp.async pipeline.
template <int MODE>
__global__ void __launch_bounds__(256, 2) gemm_sym(const float* __restrict__ Ag,
                                                   const float* __restrict__ Bg,
                                                   float* __restrict__ Cg) {
    const int b = blockIdx.z;
    const int ti = c_ti[blockIdx.x];
    const int tj = c_tj[blockIdx.x];
    const int bm = ti * 128;
    const int bn = tj * 128;
    const float* A = Ag + (size_t)b * MAT;
    const float* B = Bg + (size_t)b * MAT;
    float*       C = Cg + (size_t)b * MAT;

    const int tid = threadIdx.x;
    const int tx = tid & 15;
    const int ty = tid >> 4;

    __shared__ float As[3][128 * BK];   // row-major [m][k], 64B rows
    __shared__ float Bs[3][BK * 128];   // row-major [k][n], 512B rows

    // cp.async assignments (4 x 16B per thread per stage)
    const int ar = tid >> 2;              // A rows: ar, ar+64
    const int aq = (tid & 3) * 4;         // k-offset within row
    const int bk = tid >> 5;              // B k-rows: bk, bk+8
    const int bq = (tid & 31) * 4;        // n-offset

    const float* aSrc0 = A + (size_t)(bm + ar) * DIM + aq;
    const float* aSrc1 = aSrc0 + (size_t)64 * DIM;
    const float* bSrc0 = B + (size_t)bk * DIM + bn + bq;
    const float* bSrc1 = bSrc0 + (size_t)8 * DIM;

    const uint32_t aDstBase = smem_u32(&As[0][ar * BK + aq]);
    const uint32_t bDstBase = smem_u32(&Bs[0][bk * 128 + bq]);
    const uint32_t stageA = 128 * BK * 4;
    const uint32_t stageB = BK * 128 * 4;

    auto fill = [&](int st, int kc) {
        const uint32_t ad = aDstBase + st * stageA;
        const uint32_t bd = bDstBase + st * stageB;
        cp16(ad, aSrc0 + kc * BK);
        cp16(ad + 64 * BK * 4, aSrc1 + kc * BK);
        cp16(bd, bSrc0 + (size_t)kc * BK * DIM);
        cp16(bd + 8 * 128 * 4, bSrc1 + (size_t)kc * BK * DIM);
        asm volatile("cp.async.commit_group;" ::: "memory");
    };

    fill(0, 0);
    fill(1, 1);

    ull acc[8][4];
    #pragma unroll
    for (int i = 0; i < 8; ++i)
        #pragma unroll
        for (int p = 0; p < 4; ++p) acc[i][p] = 0ull;

    for (int kc = 0; kc < DIM / BK; ++kc) {
        const int st = kc % 3;
        if (kc < DIM / BK - 1) asm volatile("cp.async.wait_group 1;" ::: "memory");
        else                   asm volatile("cp.async.wait_group 0;" ::: "memory");
        __syncthreads();
        if (kc + 2 < DIM / BK) fill((kc + 2) % 3, kc + 2);

        const float* as = &As[st][(ty * 8) * BK];
        const float* bs = &Bs[st][tx * 8];

        #pragma unroll
        for (int kk = 0; kk < BK; ++kk) {
            ull bp[4];
            float4 b0 = *(const float4*)(bs + kk * 128);
            float4 b1 = *(const float4*)(bs + kk * 128 + 4);
            bp[0] = ((const ull*)&b0)[0];
            bp[1] = ((const ull*)&b0)[1];
            bp[2] = ((const ull*)&b1)[0];
            bp[3] = ((const ull*)&b1)[1];
            #pragma unroll
            for (int i = 0; i < 8; ++i) {
                ull ad = pkdup(as[i * BK + kk]);
                fma2(acc[i][0], ad, bp[0]);
                fma2(acc[i][1], ad, bp[1]);
                fma2(acc[i][2], ad, bp[2]);
                fma2(acc[i][3], ad, bp[3]);
            }
        }
    }

    // ---------------- epilogue ----------------
    const int r0 = bm + ty * 8;
    const int c0 = bn + tx * 8;
    float vals[8][8];
    #pragma unroll
    for (int i = 0; i < 8; ++i)
        #pragma unroll
        for (int p = 0; p < 4; ++p) {
            float2 v = upk(acc[i][p]);
            vals[i][2 * p]     = v.x;
            vals[i][2 * p + 1] = v.y;
        }
    if (MODE == 1) {
        #pragma unroll
        for (int i = 0; i < 8; ++i)
            #pragma unroll
            for (int j = 0; j < 8; ++j)
                vals[i][j] = fmaf(vals[i][j], -0.5f, (c0 + j == r0 + i) ? 1.5f : 0.0f);
    }
    // main store (rows r0.., cols c0..)
    #pragma unroll
    for (int i = 0; i < 8; ++i) {
        float4* d = (float4*)(C + (size_t)(r0 + i) * DIM + c0);
        d[0] = make_float4(vals[i][0], vals[i][1], vals[i][2], vals[i][3]);
        d[1] = make_float4(vals[i][4], vals[i][5], vals[i][6], vals[i][7]);
    }
    // mirror store (transposed) for off-diagonal tiles
    if (ti != tj) {
        #pragma unroll
        for (int j = 0; j < 8; ++j) {
            float4* d = (float4*)(C + (size_t)(c0 + j) * DIM + r0);
            d[0] = make_float4(vals[0][j], vals[1][j], vals[2][j], vals[3][j]);
            d[1] = make_float4(vals[4][j], vals[5][j], vals[6][j], vals[7][j]);
        }
    }
}

// ---------------- host launcher ----------------
extern "C" void kernel_launch(void* const* d_in, const int* in_sizes, int n_in,
                              void* d_out, int out_size) {
    const float* x = (const float*)d_in[0];
    float* out = (float*)d_out;

    float *Yb, *Zb, *Tb;
    cudaGetSymbolAddress((void**)&Yb, g_Y);
    cudaGetSymbolAddress((void**)&Zb, g_Z);
    cudaGetSymbolAddress((void**)&Tb, g_T);
    const size_t half = (size_t)BATCH * MAT;
    float* Y[2] = {Yb, Yb + half};
    float* Z[2] = {Zb, Zb + half};

    norm_kernel<<<BATCH, 256>>>(x);
    const int total4 = BATCH * MAT / 4;
    init_kernel<<<(total4 + 255) / 256, 256>>>(x, Y[0]);

    // iter 0 (Z0 = I): T0 = 1.5I - 0.5*Y0 stored as Z[0]; Y1 = Y0 @ T0
    zt_kernel<<<(total4 + 255) / 256, 256>>>(Y[0], Z[0]);

    dim3 ggrid(10, 1, BATCH);
    gemm_sym<0><<<ggrid, 256>>>(Y[0], Z[0], Y[1]);
    int ycur = 1, zcur = 0;

    for (int it = 1; it < NUM_ITER; ++it) {
        // T = 1.5 I - 0.5 * Z @ Y
        gemm_sym<1><<<ggrid, 256>>>(Z[zcur], Y[ycur], Tb);
        // Y' = Y @ T
        gemm_sym<0><<<ggrid, 256>>>(Y[ycur], Tb, Y[1 - ycur]);
        ycur ^= 1;
        if (it < NUM_ITER - 1) {
            // Z' = T @ Z
            gemm_sym<0><<<ggrid, 256>>>(Tb, Z[zcur], Z[1 - zcur]);
            zcur ^= 1;
        }
    }

    final_kernel<<<(total4 + 255) / 256, 256>>>(Y[ycur], out);
}

// round 4
// speedup vs baseline: 2.2315x; 1.1842x over previous
#include <cuda_runtime.h>
#include <cstdint>
#include <cstddef>

#define BATCH 64
#define DIM 512
#define MAT (DIM * DIM)
#define NUM_ITER 5
#define BK 32
#define NSTAGE (DIM / BK)   // 16
#define SPLIT_STRIDE 36     // 32 k + 4 pad (conflict-free fragment LDS)

typedef unsigned long long ull;

// ---------------- device scratch (allocation-free rule) ----------------
__device__ float g_Y[2][(size_t)BATCH * MAT];
__device__ float g_Z[2][(size_t)BATCH * MAT];
__device__ float g_T[(size_t)BATCH * MAT];
__device__ float g_norm[BATCH];

// upper-triangular tile pairs for 4x4 grid of 128-wide tiles
__constant__ int c_ti[10] = {0, 0, 0, 0, 1, 1, 1, 2, 2, 3};
__constant__ int c_tj[10] = {0, 1, 2, 3, 1, 2, 3, 2, 3, 3};

// smem float offsets
#define OFF_RAWA 0                    // 2 stages x 128x32
#define OFF_RAWB 8192                 // 2 stages x 128x32
#define OFF_AHI  16384                // 128 x 36
#define OFF_ALO  (OFF_AHI + 128 * SPLIT_STRIDE)
#define OFF_BHI  (OFF_ALO + 128 * SPLIT_STRIDE)
#define OFF_BLO  (OFF_BHI + 128 * SPLIT_STRIDE)
#define SMEM_FLOATS (OFF_BLO + 128 * SPLIT_STRIDE)
#define SMEM_BYTES (SMEM_FLOATS * 4)

// ---------------- helpers ----------------
__device__ __forceinline__ uint32_t smem_u32(const void* p) {
    uint32_t a;
    asm("{ .reg .u64 t; cvta.to.shared.u64 t, %1; cvt.u32.u64 %0, t; }" : "=r"(a) : "l"(p));
    return a;
}
__device__ __forceinline__ void cp16(uint32_t dst, const void* src) {
    asm volatile("cp.async.cg.shared.global [%0], [%1], 16;" :: "r"(dst), "l"(src));
}
__device__ __forceinline__ void split2(float v, uint32_t& hi, uint32_t& lo) {
    uint32_t h;
    asm("cvt.rna.tf32.f32 %0, %1;" : "=r"(h) : "f"(v));
    float hf = __uint_as_float(h);
    asm("cvt.rna.tf32.f32 %0, %1;" : "=r"(lo) : "f"(v - hf));
    hi = h;
}
__device__ __forceinline__ void mma8(float* c, uint32_t a0, uint32_t a1, uint32_t a2,
                                     uint32_t a3, uint32_t b0, uint32_t b1) {
    asm volatile(
        "mma.sync.aligned.m16n8k8.row.col.f32.tf32.tf32.f32 "
        "{%0,%1,%2,%3}, {%4,%5,%6,%7}, {%8,%9}, {%0,%1,%2,%3};"
        : "+f"(c[0]), "+f"(c[1]), "+f"(c[2]), "+f"(c[3])
        : "r"(a0), "r"(a1), "r"(a2), "r"(a3), "r"(b0), "r"(b1));
}

// ---------------- Frobenius norm per batch ----------------
__global__ void norm_kernel(const float* __restrict__ x) {
    const int b = blockIdx.x;
    const float4* xb = (const float4*)(x + (size_t)b * MAT);
    float s = 0.f;
    for (int i = threadIdx.x; i < MAT / 4; i += blockDim.x) {
        float4 v = xb[i];
        s += v.x * v.x + v.y * v.y + v.z * v.z + v.w * v.w;
    }
    __shared__ float red[8];
    #pragma unroll
    for (int o = 16; o; o >>= 1) s += __shfl_xor_sync(0xFFFFFFFFu, s, o);
    if ((threadIdx.x & 31) == 0) red[threadIdx.x >> 5] = s;
    __syncthreads();
    if (threadIdx.x < 32) {
        s = (threadIdx.x < (int)(blockDim.x >> 5)) ? red[threadIdx.x] : 0.f;
        #pragma unroll
        for (int o = 16; o; o >>= 1) s += __shfl_xor_sync(0xFFFFFFFFu, s, o);
        if (threadIdx.x == 0) g_norm[b] = sqrtf(s);
    }
}

__global__ void init_kernel(const float* __restrict__ x, float* __restrict__ Y0) {
    const int i = blockIdx.x * blockDim.x + threadIdx.x;
    if (i >= BATCH * MAT / 4) return;
    const int b = i / (MAT / 4);
    const float inv = 1.0f / g_norm[b];
    float4 v = ((const float4*)x)[i];
    v.x *= inv; v.y *= inv; v.z *= inv; v.w *= inv;
    ((float4*)Y0)[i] = v;
}

// Z1 = T0 = 1.5 I - 0.5 * Y0
__global__ void zt_kernel(const float* __restrict__ Y0, float* __restrict__ Z1) {
    const int i = blockIdx.x * blockDim.x + threadIdx.x;
    if (i >= BATCH * MAT / 4) return;
    float4 v = ((const float4*)Y0)[i];
    const int r = i % (MAT / 4);
    const int row = r / (DIM / 4);
    const int c4 = r % (DIM / 4);
    float4 o;
    o.x = -0.5f * v.x; o.y = -0.5f * v.y; o.z = -0.5f * v.z; o.w = -0.5f * v.w;
    if (c4 == (row >> 2)) ((float*)&o)[row & 3] += 1.5f;
    ((float4*)Z1)[i] = o;
}

__global__ void final_kernel(const float* __restrict__ Y, float* __restrict__ out) {
    const int i = blockIdx.x * blockDim.x + threadIdx.x;
    if (i >= BATCH * MAT / 4) return;
    const int b = i / (MAT / 4);
    const float s = sqrtf(g_norm[b]);
    float4 v = ((const float4*)Y)[i];
    v.x *= s; v.y *= s; v.z *= s; v.w *= s;
    ((float4*)out)[i] = v;
}

// ---------------- 3xTF32 mma.sync symmetric-output batched GEMM ----------------
// C = A @ B (MODE 0) or 1.5 I - 0.5 A @ B (MODE 1); A, B, C all symmetric
// (polynomials of one symmetric matrix). Tiles ti<=tj computed, off-diagonal
// mirrored. B fragments loaded from B[n][k] using B symmetry -> same layout as A.
// CTA 128x128, 256 threads, warp tile 64x32, BK=32, 2-stage cp.async raw fp32,
// in-kernel tf32 hi/lo split into padded smem planes.
template <int MODE>
__global__ void __launch_bounds__(256, 1) gemm_tc(const float* __restrict__ Ag,
                                                  const float* __restrict__ Bg,
                                                  float* __restrict__ Cg) {
    extern __shared__ float sm[];
    const int b = blockIdx.z;
    const int ti = c_ti[blockIdx.x];
    const int tj = c_tj[blockIdx.x];
    const int bm = ti * 128;
    const int bn = tj * 128;
    const float* A = Ag + (size_t)b * MAT;
    const float* B = Bg + (size_t)b * MAT;
    float*       C = Cg + (size_t)b * MAT;

    const int tid = threadIdx.x;
    const int wid = tid >> 5;
    const int lane = tid & 31;
    const int gid = lane >> 2;   // 0..7
    const int tig = lane & 3;    // 0..3
    const int wm = wid >> 2;     // 0..1 : row block of 64
    const int wn = wid & 3;      // 0..3 : col block of 32

    const uint32_t s_rawA = smem_u32(sm + OFF_RAWA);
    const uint32_t s_rawB = smem_u32(sm + OFF_RAWB);

    // cp.async: 4 chunks of A rows + 4 of B rows (B read as B[n][k] via symmetry)
    auto fill = [&](int stage, int kc) {
        const uint32_t da = s_rawA + (stage & 1) * 4096 * 4;
        const uint32_t db = s_rawB + (stage & 1) * 4096 * 4;
        const size_t koff = (size_t)kc * BK;
        #pragma unroll
        for (int j = 0; j < 4; ++j) {
            const int ch = tid + 256 * j;        // 0..1023
            const int row = ch >> 3;
            const int c8 = (ch & 7) * 4;
            cp16(da + (row * 32 + c8) * 4, A + (size_t)(bm + row) * DIM + koff + c8);
            cp16(db + (row * 32 + c8) * 4, B + (size_t)(bn + row) * DIM + koff + c8);
        }
        asm volatile("cp.async.commit_group;" ::: "memory");
    };

    fill(0, 0);

    float acc[4][4][4];
    #pragma unroll
    for (int mf = 0; mf < 4; ++mf)
        #pragma unroll
        for (int nf = 0; nf < 4; ++nf)
            #pragma unroll
            for (int e = 0; e < 4; ++e) acc[mf][nf][e] = 0.f;

    for (int s = 0; s < NSTAGE; ++s) {
        if (s + 1 < NSTAGE) {
            fill(s + 1, s + 1);
            asm volatile("cp.async.wait_group 1;" ::: "memory");
        } else {
            asm volatile("cp.async.wait_group 0;" ::: "memory");
        }
        __syncthreads();

        // split pass: raw fp32 -> tf32 hi/lo planes (stride 36)
        {
            const float* ra = sm + OFF_RAWA + (s & 1) * 4096;
            const float* rb = sm + OFF_RAWB + (s & 1) * 4096;
            #pragma unroll
            for (int j = 0; j < 4; ++j) {
                const int f = tid + 256 * j;    // float4 id 0..1023
                const int row = f >> 3;
                const int c4 = (f & 7) * 4;
                const int rsrc = row * 32 + c4;
                const int rdst = row * SPLIT_STRIDE + c4;
                float4 va = *(const float4*)(ra + rsrc);
                float4 vb = *(const float4*)(rb + rsrc);
                uint4 h, l;
                split2(va.x, h.x, l.x); split2(va.y, h.y, l.y);
                split2(va.z, h.z, l.z); split2(va.w, h.w, l.w);
                *(uint4*)(sm + OFF_AHI + rdst) = h;
                *(uint4*)(sm + OFF_ALO + rdst) = l;
                split2(vb.x, h.x, l.x); split2(vb.y, h.y, l.y);
                split2(vb.z, h.z, l.z); split2(vb.w, h.w, l.w);
                *(uint4*)(sm + OFF_BHI + rdst) = h;
                *(uint4*)(sm + OFF_BLO + rdst) = l;
            }
        }
        __syncthreads();

        const uint32_t* ahi = (const uint32_t*)(sm + OFF_AHI);
        const uint32_t* alo = (const uint32_t*)(sm + OFF_ALO);
        const uint32_t* bhi = (const uint32_t*)(sm + OFF_BHI);
        const uint32_t* blo = (const uint32_t*)(sm + OFF_BLO);

        #pragma unroll
        for (int k8 = 0; k8 < BK / 8; ++k8) {
            const int kb = k8 * 8 + tig;
            // A fragments: rows wm*64 + mf*16 + gid (+8)
            uint32_t Ah[4][4], Al[4][4];
            #pragma unroll
            for (int mf = 0; mf < 4; ++mf) {
                const int r0 = (wm * 64 + mf * 16 + gid) * SPLIT_STRIDE + kb;
                const int r1 = r0 + 8 * SPLIT_STRIDE;
                Ah[mf][0] = ahi[r0];     Ah[mf][1] = ahi[r1];
                Ah[mf][2] = ahi[r0 + 4]; Ah[mf][3] = ahi[r1 + 4];
                Al[mf][0] = alo[r0];     Al[mf][1] = alo[r1];
                Al[mf][2] = alo[r0 + 4]; Al[mf][3] = alo[r1 + 4];
            }
            // B fragments: cols wn*32 + nf*8 + gid (loaded from B[n][k])
            uint32_t Bh[4][2], Bl[4][2];
            #pragma unroll
            for (int nf = 0; nf < 4; ++nf) {
                const int r0 = (wn * 32 + nf * 8 + gid) * SPLIT_STRIDE + kb;
                Bh[nf][0] = bhi[r0]; Bh[nf][1] = bhi[r0 + 4];
                Bl[nf][0] = blo[r0]; Bl[nf][1] = blo[r0 + 4];
            }
            #pragma unroll
            for (int mf = 0; mf < 4; ++mf)
                #pragma unroll
                for (int nf = 0; nf < 4; ++nf) {
                    mma8(acc[mf][nf], Ah[mf][0], Ah[mf][1], Ah[mf][2], Ah[mf][3],
                         Bh[nf][0], Bh[nf][1]);
                    mma8(acc[mf][nf], Ah[mf][0], Ah[mf][1], Ah[mf][2], Ah[mf][3],
                         Bl[nf][0], Bl[nf][1]);
                    mma8(acc[mf][nf], Al[mf][0], Al[mf][1], Al[mf][2], Al[mf][3],
                         Bh[nf][0], Bh[nf][1]);
                }
        }
    }

    // ---------------- epilogue ----------------
    #pragma unroll
    for (int mf = 0; mf < 4; ++mf) {
        #pragma unroll
        for (int nf = 0; nf < 4; ++nf) {
            float* cr = acc[mf][nf];
            const int r0 = bm + wm * 64 + mf * 16 + gid;
            const int r1 = r0 + 8;
            const int cb = bn + wn * 32 + nf * 8 + 2 * tig;
            if (MODE == 1) {
                cr[0] = fmaf(cr[0], -0.5f, (cb == r0)     ? 1.5f : 0.0f);
                cr[1] = fmaf(cr[1], -0.5f, (cb + 1 == r0) ? 1.5f : 0.0f);
                cr[2] = fmaf(cr[2], -0.5f, (cb == r1)     ? 1.5f : 0.0f);
                cr[3] = fmaf(cr[3], -0.5f, (cb + 1 == r1) ? 1.5f : 0.0f);
            }
            *(float2*)(C + (size_t)r0 * DIM + cb) = make_float2(cr[0], cr[1]);
            *(float2*)(C + (size_t)r1 * DIM + cb) = make_float2(cr[2], cr[3]);
            if (ti != tj) {  // mirror transposed
                C[(size_t)cb * DIM + r0]       = cr[0];
                C[(size_t)(cb + 1) * DIM + r0] = cr[1];
                C[(size_t)cb * DIM + r1]       = cr[2];
                C[(size_t)(cb + 1) * DIM + r1] = cr[3];
            }
        }
    }
}

// ---------------- host launcher ----------------
extern "C" void kernel_launch(void* const* d_in, const int* in_sizes, int n_in,
                              void* d_out, int out_size) {
    const float* x = (const float*)d_in[0];
    float* out = (float*)d_out;

    float *Yb, *Zb, *Tb;
    cudaGetSymbolAddress((void**)&Yb, g_Y);
    cudaGetSymbolAddress((void**)&Zb, g_Z);
    cudaGetSymbolAddress((void**)&Tb, g_T);
    const size_t half = (size_t)BATCH * MAT;
    float* Y[2] = {Yb, Yb + half};
    float* Z[2] = {Zb, Zb + half};

    cudaFuncSetAttribute(gemm_tc<0>, cudaFuncAttributeMaxDynamicSharedMemorySize, SMEM_BYTES);
    cudaFuncSetAttribute(gemm_tc<1>, cudaFuncAttributeMaxDynamicSharedMemorySize, SMEM_BYTES);

    norm_kernel<<<BATCH, 256>>>(x);
    const int total4 = BATCH * MAT / 4;
    init_kernel<<<(total4 + 255) / 256, 256>>>(x, Y[0]);

    // iter 0 (Z0 = I): T0 = 1.5I - 0.5*Y0 stored as Z[0]; Y1 = Y0 @ T0
    zt_kernel<<<(total4 + 255) / 256, 256>>>(Y[0], Z[0]);

    dim3 ggrid(10, 1, BATCH);
    gemm_tc<0><<<ggrid, 256, SMEM_BYTES>>>(Y[0], Z[0], Y[1]);
    int ycur = 1, zcur = 0;

    for (int it = 1; it < NUM_ITER; ++it) {
        gemm_tc<1><<<ggrid, 256, SMEM_BYTES>>>(Z[zcur], Y[ycur], Tb);
        gemm_tc<0><<<ggrid, 256, SMEM_BYTES>>>(Y[ycur], Tb, Y[1 - ycur]);
        ycur ^= 1;
        if (it < NUM_ITER - 1) {
            gemm_tc<0><<<ggrid, 256, SMEM_BYTES>>>(Tb, Z[zcur], Z[1 - zcur]);
            zcur ^= 1;
        }
    }

    final_kernel<<<(total4 + 255) / 256, 256>>>(Y[ycur], out);
}